// round 4
// baseline (speedup 1.0000x reference)
#include <cuda_runtime.h>
#include <cstdint>
#include <cstddef>

typedef unsigned long long ull;

#define THREADS 512
#define TM      64
#define KD      64
#define H       100
#define HP      128
#define NOUT    384
#define SXS     68    // x row stride (float4-aligned, conflict-optimal)
#define SH      100   // h row stride (float4-aligned, conflict-optimal)
#define SY      68    // y1 staging stride

// shared memory float offsets
#define OFF_H1  0                 // 64*100 = 6400
#define OFF_H2  6400              // 64*100 = 6400
#define OFF_P   12800             // phase pool, 12800 floats
#define OFF_X   OFF_P             // 64*68 = 4352   (phase A)
#define OFF_W1  (OFF_P + 4352)    // 64*128 = 8192  (phase A)
#define OFF_W4  OFF_P             // 100*128 = 12800 (phase B)
#define OFF_W2C OFF_P             // 20*384 = 7680  (phase C, permuted cols)
#define OFF_SY1 (OFF_P + 7680)    // 64*68 = 4352   (epilogue y1 logits)
#define OFF_B1  (OFF_P + 12800)   // 128
#define OFF_B4  (OFF_B1 + 128)    // 128
#define OFF_B2  (OFF_B4 + 128)    // 384 (permuted)
#define SM_FLOATS (OFF_B2 + 384)  // 26240
#define SMEM_BYTES (SM_FLOATS * 4) // 104960

__device__ __forceinline__ ull pk2(float lo, float hi) {
    ull r; asm("mov.b64 %0,{%1,%2};" : "=l"(r) : "f"(lo), "f"(hi)); return r;
}
__device__ __forceinline__ void upk2(ull v, float& lo, float& hi) {
    asm("mov.b64 {%0,%1},%2;" : "=f"(lo), "=f"(hi) : "l"(v));
}
__device__ __forceinline__ ull ffma2(ull a, ull b, ull c) {
    ull d; asm("fma.rn.f32x2 %0,%1,%2,%3;" : "=l"(d) : "l"(a), "l"(b), "l"(c)); return d;
}

// accurate exp, fast-math-proof (no MUFU)
__device__ __forceinline__ float my_expf(float z) {
    float kf = rintf(z * 1.4426950408889634f);
    float r  = fmaf(kf, -0.693145751953125f, z);
    r        = fmaf(kf, -1.42860677e-6f,     r);
    float p  = 1.9841270e-4f;
    p = fmaf(p, r, 1.3888889e-3f);
    p = fmaf(p, r, 8.3333338e-3f);
    p = fmaf(p, r, 4.1666668e-2f);
    p = fmaf(p, r, 1.6666667e-1f);
    p = fmaf(p, r, 0.5f);
    p = fmaf(p, r, 1.0f);
    p = fmaf(p, r, 1.0f);
    int ik = (int)kf;
    return p * __int_as_float((ik + 127) << 23);
}
// accurate tanh (~1e-7 abs), fast-math-proof
__device__ __forceinline__ float my_tanhf(float x) {
    float ax = fminf(fabsf(x), 10.0f);
    float e  = my_expf(2.0f * ax);
    float rc = __frcp_rn(e + 1.0f);
    float th = fmaf(-2.0f, rc, 1.0f);
    return (x < 0.0f) ? -th : th;
}

// GEMM-C permuted column index: warp w owns [24w,24w+24) =
//   y1 cols 4w..4w+3  then  y2 cols 64+20w..64+20w+19 (4 full segments)
__device__ __forceinline__ int permC(int c) {
    if (c < KD) return (c >> 2) * 24 + (c & 3);
    int cc = c - KD;
    return (cc / 20) * 24 + 4 + (cc % 20);
}

__global__ void __launch_bounds__(THREADS, 1)
fused_mlp_gumbel(const float* __restrict__ x,  const float* __restrict__ W1,
                 const float* __restrict__ b1, const float* __restrict__ W4,
                 const float* __restrict__ b4, const float* __restrict__ W2,
                 const float* __restrict__ b2, const float* __restrict__ gum,
                 float* __restrict__ out)
{
    extern __shared__ float sm[];
    const int tid  = threadIdx.x;
    const int warp = tid >> 5;
    const int lane = tid & 31;
    const int row0 = blockIdx.x * TM;

    // ---- W4 prefetch into registers (latency hidden under GEMM A) ----
    float w4r[20];
#pragma unroll
    for (int j = 0; j < 20; j++) {
        int idx = tid + j * THREADS;
        w4r[j] = (idx < H * H) ? W4[idx] : 0.0f;
    }

    // ---- phase A loads: x tile (vectorized), W1 padded, biases ----
    {
        const float4* xg = (const float4*)(x + (size_t)row0 * KD);
#pragma unroll 2
        for (int i = tid; i < TM * KD / 4; i += THREADS) {
            int r = i >> 4, k4 = i & 15;
            *(float4*)(sm + OFF_X + r * SXS + k4 * 4) = xg[i];
        }
    }
    for (int i = tid; i < KD * HP; i += THREADS) {
        int k = i >> 7, c = i & 127;
        sm[OFF_W1 + i] = (c < H) ? W1[k * H + c] : 0.0f;
    }
    for (int i = tid; i < HP; i += THREADS) {
        sm[OFF_B1 + i] = (i < H) ? b1[i] : 0.0f;
        sm[OFF_B4 + i] = (i < H) ? b4[i] : 0.0f;
    }
    for (int i = tid; i < NOUT; i += THREADS) sm[OFF_B2 + permC(i)] = b2[i];
    __syncthreads();

    // ---- GEMM A: h1 = tanh(x @ W1 + b1), warp owns 8 cols ----
    {
        const int c0 = warp * 8;
        const ulonglong2* bb = (const ulonglong2*)(sm + OFF_B1 + c0);
        ulonglong2 a0[2], a1[2];
        a0[0] = bb[0]; a0[1] = bb[1]; a1[0] = bb[0]; a1[1] = bb[1];
        const float* xr0 = sm + OFF_X + lane * SXS;
        const float* xr1 = sm + OFF_X + (lane + 32) * SXS;
#pragma unroll
        for (int k4 = 0; k4 < KD; k4 += 4) {
            float4 ha = *(const float4*)(xr0 + k4);
            float4 hb = *(const float4*)(xr1 + k4);
            float av[4] = {ha.x, ha.y, ha.z, ha.w};
            float bv[4] = {hb.x, hb.y, hb.z, hb.w};
#pragma unroll
            for (int q = 0; q < 4; q++) {
                ull xa = pk2(av[q], av[q]), xb = pk2(bv[q], bv[q]);
                const ulonglong2* wp = (const ulonglong2*)(sm + OFF_W1 + (k4 + q) * HP + c0);
                ulonglong2 w0 = wp[0], w1 = wp[1];
                a0[0].x = ffma2(xa, w0.x, a0[0].x); a0[0].y = ffma2(xa, w0.y, a0[0].y);
                a0[1].x = ffma2(xa, w1.x, a0[1].x); a0[1].y = ffma2(xa, w1.y, a0[1].y);
                a1[0].x = ffma2(xb, w0.x, a1[0].x); a1[0].y = ffma2(xb, w0.y, a1[0].y);
                a1[1].x = ffma2(xb, w1.x, a1[1].x); a1[1].y = ffma2(xb, w1.y, a1[1].y);
            }
        }
        float v[8];
        upk2(a0[0].x, v[0], v[1]); upk2(a0[0].y, v[2], v[3]);
        upk2(a0[1].x, v[4], v[5]); upk2(a0[1].y, v[6], v[7]);
        if (c0 + 8 <= H) {
            float4 lo = {my_tanhf(v[0]), my_tanhf(v[1]), my_tanhf(v[2]), my_tanhf(v[3])};
            float4 hi = {my_tanhf(v[4]), my_tanhf(v[5]), my_tanhf(v[6]), my_tanhf(v[7])};
            *(float4*)(sm + OFF_H1 + lane * SH + c0) = lo;
            *(float4*)(sm + OFF_H1 + lane * SH + c0 + 4) = hi;
        } else if (c0 < H) {
            float4 lo = {my_tanhf(v[0]), my_tanhf(v[1]), my_tanhf(v[2]), my_tanhf(v[3])};
            *(float4*)(sm + OFF_H1 + lane * SH + c0) = lo;
        }
        upk2(a1[0].x, v[0], v[1]); upk2(a1[0].y, v[2], v[3]);
        upk2(a1[1].x, v[4], v[5]); upk2(a1[1].y, v[6], v[7]);
        if (c0 + 8 <= H) {
            float4 lo = {my_tanhf(v[0]), my_tanhf(v[1]), my_tanhf(v[2]), my_tanhf(v[3])};
            float4 hi = {my_tanhf(v[4]), my_tanhf(v[5]), my_tanhf(v[6]), my_tanhf(v[7])};
            *(float4*)(sm + OFF_H1 + (lane + 32) * SH + c0) = lo;
            *(float4*)(sm + OFF_H1 + (lane + 32) * SH + c0 + 4) = hi;
        } else if (c0 < H) {
            float4 lo = {my_tanhf(v[0]), my_tanhf(v[1]), my_tanhf(v[2]), my_tanhf(v[3])};
            *(float4*)(sm + OFF_H1 + (lane + 32) * SH + c0) = lo;
        }
    }
    __syncthreads();   // h1 done, X/W1 region dead

    // ---- store W4 (padded) from regs, zero-fill pad cols ----
#pragma unroll
    for (int j = 0; j < 20; j++) {
        int idx = tid + j * THREADS;
        if (idx < H * H) {
            int k = idx / H, c = idx - k * H;
            sm[OFF_W4 + k * HP + c] = w4r[j];
        }
    }
    for (int i = tid; i < H * (HP - H); i += THREADS) {
        int k = i / (HP - H), c = H + (i - k * (HP - H));
        sm[OFF_W4 + k * HP + c] = 0.0f;
    }
    // prefetch W2 chunk 0 (hidden under GEMM B)
    const float4* wg = (const float4*)W2;
    float4 pf[4];
#pragma unroll
    for (int j = 0; j < 4; j++) {
        int idx = tid + j * THREADS;
        if (idx < 1920) pf[j] = wg[idx];
    }
    __syncthreads();

    // ---- GEMM B: h2 = tanh(h1 @ W4 + b4) ----
    {
        const int c0 = warp * 8;
        const ulonglong2* bb = (const ulonglong2*)(sm + OFF_B4 + c0);
        ulonglong2 a0[2], a1[2];
        a0[0] = bb[0]; a0[1] = bb[1]; a1[0] = bb[0]; a1[1] = bb[1];
        const float* h0 = sm + OFF_H1 + lane * SH;
        const float* h1r = sm + OFF_H1 + (lane + 32) * SH;
#pragma unroll 5
        for (int k4 = 0; k4 < H; k4 += 4) {
            float4 ha = *(const float4*)(h0 + k4);
            float4 hb = *(const float4*)(h1r + k4);
            float av[4] = {ha.x, ha.y, ha.z, ha.w};
            float bv[4] = {hb.x, hb.y, hb.z, hb.w};
#pragma unroll
            for (int q = 0; q < 4; q++) {
                ull xa = pk2(av[q], av[q]), xb = pk2(bv[q], bv[q]);
                const ulonglong2* wp = (const ulonglong2*)(sm + OFF_W4 + (k4 + q) * HP + c0);
                ulonglong2 w0 = wp[0], w1 = wp[1];
                a0[0].x = ffma2(xa, w0.x, a0[0].x); a0[0].y = ffma2(xa, w0.y, a0[0].y);
                a0[1].x = ffma2(xa, w1.x, a0[1].x); a0[1].y = ffma2(xa, w1.y, a0[1].y);
                a1[0].x = ffma2(xb, w0.x, a1[0].x); a1[0].y = ffma2(xb, w0.y, a1[0].y);
                a1[1].x = ffma2(xb, w1.x, a1[1].x); a1[1].y = ffma2(xb, w1.y, a1[1].y);
            }
        }
        float v[8];
        upk2(a0[0].x, v[0], v[1]); upk2(a0[0].y, v[2], v[3]);
        upk2(a0[1].x, v[4], v[5]); upk2(a0[1].y, v[6], v[7]);
        if (c0 + 8 <= H) {
            float4 lo = {my_tanhf(v[0]), my_tanhf(v[1]), my_tanhf(v[2]), my_tanhf(v[3])};
            float4 hi = {my_tanhf(v[4]), my_tanhf(v[5]), my_tanhf(v[6]), my_tanhf(v[7])};
            *(float4*)(sm + OFF_H2 + lane * SH + c0) = lo;
            *(float4*)(sm + OFF_H2 + lane * SH + c0 + 4) = hi;
        } else if (c0 < H) {
            float4 lo = {my_tanhf(v[0]), my_tanhf(v[1]), my_tanhf(v[2]), my_tanhf(v[3])};
            *(float4*)(sm + OFF_H2 + lane * SH + c0) = lo;
        }
        upk2(a1[0].x, v[0], v[1]); upk2(a1[0].y, v[2], v[3]);
        upk2(a1[1].x, v[4], v[5]); upk2(a1[1].y, v[6], v[7]);
        if (c0 + 8 <= H) {
            float4 lo = {my_tanhf(v[0]), my_tanhf(v[1]), my_tanhf(v[2]), my_tanhf(v[3])};
            float4 hi = {my_tanhf(v[4]), my_tanhf(v[5]), my_tanhf(v[6]), my_tanhf(v[7])};
            *(float4*)(sm + OFF_H2 + (lane + 32) * SH + c0) = lo;
            *(float4*)(sm + OFF_H2 + (lane + 32) * SH + c0 + 4) = hi;
        } else if (c0 < H) {
            float4 lo = {my_tanhf(v[0]), my_tanhf(v[1]), my_tanhf(v[2]), my_tanhf(v[3])};
            *(float4*)(sm + OFF_H2 + (lane + 32) * SH + c0) = lo;
        }
    }
    __syncthreads();   // h2 done, W4 region dead

    // ---- store W2 chunk 0 (permuted cols) ----
#pragma unroll
    for (int j = 0; j < 4; j++) {
        int idx = tid + j * THREADS;
        if (idx < 1920) {
            int k = idx / 96, c4 = (idx - k * 96) * 4;
            int p;
            if (c4 < KD) p = (c4 >> 2) * 24;
            else { int cc = c4 - KD; p = (cc / 20) * 24 + 4 + (cc % 20); }
            *(float4*)(sm + OFF_W2C + k * NOUT + p) = pf[j];
        }
    }
    __syncthreads();

    // ---- GEMM C: out = h2 @ W2 + b2, 5 k-chunks of 20, register-prefetched ----
    const int cw = warp * 24;
    ulonglong2 A0[6], A1[6];
    {
        const ulonglong2* bb = (const ulonglong2*)(sm + OFF_B2 + cw);
#pragma unroll
        for (int j = 0; j < 6; j++) { A0[j] = bb[j]; A1[j] = bb[j]; }
    }
    for (int ch = 0; ch < 5; ch++) {
        if (ch < 4) {
#pragma unroll
            for (int j = 0; j < 4; j++) {
                int idx = tid + j * THREADS;
                if (idx < 1920) pf[j] = wg[(ch + 1) * 1920 + idx];
            }
        }
        const float* h0 = sm + OFF_H2 + lane * SH + ch * 20;
        const float* h1r = sm + OFF_H2 + (lane + 32) * SH + ch * 20;
#pragma unroll
        for (int kq = 0; kq < 20; kq += 4) {
            float4 ha = *(const float4*)(h0 + kq);
            float4 hb = *(const float4*)(h1r + kq);
            float av[4] = {ha.x, ha.y, ha.z, ha.w};
            float bv[4] = {hb.x, hb.y, hb.z, hb.w};
#pragma unroll
            for (int q = 0; q < 4; q++) {
                ull xa = pk2(av[q], av[q]), xb = pk2(bv[q], bv[q]);
                const ulonglong2* wp = (const ulonglong2*)(sm + OFF_W2C + (kq + q) * NOUT + cw);
#pragma unroll
                for (int j = 0; j < 6; j++) {
                    ulonglong2 w = wp[j];
                    A0[j].x = ffma2(xa, w.x, A0[j].x); A0[j].y = ffma2(xa, w.y, A0[j].y);
                    A1[j].x = ffma2(xb, w.x, A1[j].x); A1[j].y = ffma2(xb, w.y, A1[j].y);
                }
            }
        }
        if (ch < 4) {
            __syncthreads();   // everyone done reading this chunk
#pragma unroll
            for (int j = 0; j < 4; j++) {
                int idx = tid + j * THREADS;
                if (idx < 1920) {
                    int k = idx / 96, c4 = (idx - k * 96) * 4;
                    int p;
                    if (c4 < KD) p = (c4 >> 2) * 24;
                    else { int cc = c4 - KD; p = (cc / 20) * 24 + 4 + (cc % 20); }
                    *(float4*)(sm + OFF_W2C + k * NOUT + p) = pf[j];
                }
            }
            __syncthreads();
        }
    }

    // ---- epilogue ----
    float r0v[24], r1v[24];
#pragma unroll
    for (int j = 0; j < 6; j++) {
        upk2(A0[j].x, r0v[4 * j + 0], r0v[4 * j + 1]);
        upk2(A0[j].y, r0v[4 * j + 2], r0v[4 * j + 3]);
        upk2(A1[j].x, r1v[4 * j + 0], r1v[4 * j + 1]);
        upk2(A1[j].y, r1v[4 * j + 2], r1v[4 * j + 3]);
    }
    // stage y1 logits (4 per warp per row) to smem
    {
        float4 s0 = {r0v[0], r0v[1], r0v[2], r0v[3]};
        float4 s1 = {r1v[0], r1v[1], r1v[2], r1v[3]};
        *(float4*)(sm + OFF_SY1 + lane * SY + warp * 4) = s0;
        *(float4*)(sm + OFF_SY1 + (lane + 32) * SY + warp * 4) = s1;
    }
    // prefetch gumbel for this warp's 4 segments x 2 rows
    const float* g0 = gum + (size_t)(row0 + lane) * (KD * 5) + warp * 20;
    const float* g1 = gum + (size_t)(row0 + lane + 32) * (KD * 5) + warp * 20;
    float4 ga[5], gb[5];
#pragma unroll
    for (int s = 0; s < 5; s++) { ga[s] = *(const float4*)(g0 + 4 * s); gb[s] = *(const float4*)(g1 + 4 * s); }
    __syncthreads();

    // y1 softmax: 8 threads per row over 64 logits, write straight to global
    {
        const int row = tid >> 3, sub = tid & 7;
        const float* yr = sm + OFF_SY1 + row * SY;
        float4 v0 = *(const float4*)(yr + sub * 8);
        float4 v1 = *(const float4*)(yr + sub * 8 + 4);
        float vv[8] = {v0.x, v0.y, v0.z, v0.w, v1.x, v1.y, v1.z, v1.w};
        float mx = vv[0];
#pragma unroll
        for (int j = 1; j < 8; j++) mx = fmaxf(mx, vv[j]);
#pragma unroll
        for (int d = 1; d < 8; d <<= 1) mx = fmaxf(mx, __shfl_xor_sync(0xFFFFFFFFu, mx, d));
        float s = 0.0f;
#pragma unroll
        for (int j = 0; j < 8; j++) { vv[j] = my_expf(fmaxf(vv[j] - mx, -80.0f)); s += vv[j]; }
#pragma unroll
        for (int d = 1; d < 8; d <<= 1) s += __shfl_xor_sync(0xFFFFFFFFu, s, d);
        float rs = __frcp_rn(s);
        float* og = out + (size_t)(row0 + row) * NOUT + sub * 8;
        float4 o0 = {vv[0] * rs, vv[1] * rs, vv[2] * rs, vv[3] * rs};
        float4 o1 = {vv[4] * rs, vv[5] * rs, vv[6] * rs, vv[7] * rs};
        *(float4*)og = o0;
        *(float4*)(og + 4) = o1;
    }

    // y2: one-hot argmax over 4 segments x 2 rows, straight to global
    {
        float gaf[20], gbf[20];
#pragma unroll
        for (int s = 0; s < 5; s++) {
            gaf[4 * s] = ga[s].x; gaf[4 * s + 1] = ga[s].y; gaf[4 * s + 2] = ga[s].z; gaf[4 * s + 3] = ga[s].w;
            gbf[4 * s] = gb[s].x; gbf[4 * s + 1] = gb[s].y; gbf[4 * s + 2] = gb[s].z; gbf[4 * s + 3] = gb[s].w;
        }
        float ov[20];
#pragma unroll
        for (int s = 0; s < 4; s++) {
            float best = r0v[4 + 5 * s] + gaf[5 * s];
            int arg = 0;
#pragma unroll
            for (int m = 1; m < 5; m++) {
                float val = r0v[4 + 5 * s + m] + gaf[5 * s + m];
                if (val > best) { best = val; arg = m; }
            }
#pragma unroll
            for (int m = 0; m < 5; m++) ov[5 * s + m] = (m == arg) ? 1.0f : 0.0f;
        }
        float* o0p = out + (size_t)(row0 + lane) * NOUT + KD + warp * 20;
#pragma unroll
        for (int s = 0; s < 5; s++) {
            float4 w = {ov[4 * s], ov[4 * s + 1], ov[4 * s + 2], ov[4 * s + 3]};
            *(float4*)(o0p + 4 * s) = w;
        }
#pragma unroll
        for (int s = 0; s < 4; s++) {
            float best = r1v[4 + 5 * s] + gbf[5 * s];
            int arg = 0;
#pragma unroll
            for (int m = 1; m < 5; m++) {
                float val = r1v[4 + 5 * s + m] + gbf[5 * s + m];
                if (val > best) { best = val; arg = m; }
            }
#pragma unroll
            for (int m = 0; m < 5; m++) ov[5 * s + m] = (m == arg) ? 1.0f : 0.0f;
        }
        float* o1p = out + (size_t)(row0 + lane + 32) * NOUT + KD + warp * 20;
#pragma unroll
        for (int s = 0; s < 5; s++) {
            float4 w = {ov[4 * s], ov[4 * s + 1], ov[4 * s + 2], ov[4 * s + 3]};
            *(float4*)(o1p + 4 * s) = w;
        }
    }
}

extern "C" void kernel_launch(void* const* d_in, const int* in_sizes, int n_in,
                              void* d_out, int out_size) {
    const float* x   = (const float*)d_in[0];
    const float* W1  = (const float*)d_in[1];
    const float* b1  = (const float*)d_in[2];
    const float* W4  = (const float*)d_in[3];
    const float* b4  = (const float*)d_in[4];
    const float* W2  = (const float*)d_in[5];
    const float* b2  = (const float*)d_in[6];
    const float* gum = (const float*)d_in[7];
    float* out = (float*)d_out;

    int B = in_sizes[0] / KD;
    int grid = B / TM;

    cudaFuncSetAttribute(fused_mlp_gumbel,
                         cudaFuncAttributeMaxDynamicSharedMemorySize, SMEM_BYTES);
    fused_mlp_gumbel<<<grid, THREADS, SMEM_BYTES>>>(x, W1, b1, W4, b4, W2, b2, gum, out);
}

// round 6
// speedup vs baseline: 1.0032x; 1.0032x over previous
#include <cuda_runtime.h>
#include <cstdint>
#include <cstddef>

typedef unsigned long long ull;

#define THREADS 512
#define TM      64
#define KD      64
#define H       100
#define HP      128
#define NOUT    384
#define SXS     68    // x row stride (float4-aligned, conflict-optimal)
#define SH      100   // h row stride (float4-aligned, conflict-optimal)
#define SY      68    // y1 staging stride

// shared memory float offsets
#define OFF_H1  0                 // 64*100 = 6400
#define OFF_H2  6400              // 64*100 = 6400
#define OFF_P   12800             // phase pool, 12800 floats
#define OFF_X   OFF_P             // 64*68 = 4352   (phase A)
#define OFF_W1  (OFF_P + 4352)    // 64*128 = 8192  (phase A)
#define OFF_W4  OFF_P             // 100*128 = 12800 (phase B)
#define OFF_W2C OFF_P             // 20*384 = 7680  (phase C, permuted cols)
#define OFF_SY1 (OFF_P + 7680)    // 64*68 = 4352   (epilogue y1 logits)
#define OFF_B1  (OFF_P + 12800)   // 128
#define OFF_B4  (OFF_B1 + 128)    // 128
#define OFF_B2  (OFF_B4 + 128)    // 384 (permuted)
#define SM_FLOATS (OFF_B2 + 384)  // 26240
#define SMEM_BYTES (SM_FLOATS * 4) // 104960

__device__ __forceinline__ ull pk2(float lo, float hi) {
    ull r; asm("mov.b64 %0,{%1,%2};" : "=l"(r) : "f"(lo), "f"(hi)); return r;
}
__device__ __forceinline__ void upk2(ull v, float& lo, float& hi) {
    asm("mov.b64 {%0,%1},%2;" : "=f"(lo), "=f"(hi) : "l"(v));
}
__device__ __forceinline__ ull ffma2(ull a, ull b, ull c) {
    ull d; asm("fma.rn.f32x2 %0,%1,%2,%3;" : "=l"(d) : "l"(a), "l"(b), "l"(c)); return d;
}

// accurate exp, fast-math-proof (no MUFU)
__device__ __forceinline__ float my_expf(float z) {
    float kf = rintf(z * 1.4426950408889634f);
    float r  = fmaf(kf, -0.693145751953125f, z);
    r        = fmaf(kf, -1.42860677e-6f,     r);
    float p  = 1.9841270e-4f;
    p = fmaf(p, r, 1.3888889e-3f);
    p = fmaf(p, r, 8.3333338e-3f);
    p = fmaf(p, r, 4.1666668e-2f);
    p = fmaf(p, r, 1.6666667e-1f);
    p = fmaf(p, r, 0.5f);
    p = fmaf(p, r, 1.0f);
    p = fmaf(p, r, 1.0f);
    int ik = (int)kf;
    return p * __int_as_float((ik + 127) << 23);
}
// accurate tanh (~1e-7 abs), fast-math-proof
__device__ __forceinline__ float my_tanhf(float x) {
    float ax = fminf(fabsf(x), 10.0f);
    float e  = my_expf(2.0f * ax);
    float rc = __frcp_rn(e + 1.0f);
    float th = fmaf(-2.0f, rc, 1.0f);
    return (x < 0.0f) ? -th : th;
}

// GEMM-C permuted column index: warp w owns [24w,24w+24) =
//   y1 cols 4w..4w+3  then  y2 cols 64+20w..64+20w+19 (4 full segments)
__device__ __forceinline__ int permC(int c) {
    if (c < KD) return (c >> 2) * 24 + (c & 3);
    int cc = c - KD;
    return (cc / 20) * 24 + 4 + (cc % 20);
}

__global__ void __launch_bounds__(THREADS, 1)
fused_mlp_gumbel(const float* __restrict__ x,  const float* __restrict__ W1,
                 const float* __restrict__ b1, const float* __restrict__ W4,
                 const float* __restrict__ b4, const float* __restrict__ W2,
                 const float* __restrict__ b2, const float* __restrict__ gum,
                 float* __restrict__ out)
{
    extern __shared__ float sm[];
    const int tid  = threadIdx.x;
    const int warp = tid >> 5;
    const int lane = tid & 31;
    const int row0 = blockIdx.x * TM;

    // ---- W4 prefetch into registers (latency hidden under GEMM A) ----
    float w4r[20];
#pragma unroll
    for (int j = 0; j < 20; j++) {
        int idx = tid + j * THREADS;
        w4r[j] = (idx < H * H) ? W4[idx] : 0.0f;
    }

    // ---- phase A loads: x tile (vectorized), W1 padded, biases ----
    {
        const float4* xg = (const float4*)(x + (size_t)row0 * KD);
#pragma unroll 2
        for (int i = tid; i < TM * KD / 4; i += THREADS) {
            int r = i >> 4, k4 = i & 15;
            *(float4*)(sm + OFF_X + r * SXS + k4 * 4) = xg[i];
        }
    }
    for (int i = tid; i < KD * HP; i += THREADS) {
        int k = i >> 7, c = i & 127;
        sm[OFF_W1 + i] = (c < H) ? W1[k * H + c] : 0.0f;
    }
    for (int i = tid; i < HP; i += THREADS) {
        sm[OFF_B1 + i] = (i < H) ? b1[i] : 0.0f;
        sm[OFF_B4 + i] = (i < H) ? b4[i] : 0.0f;
    }
    for (int i = tid; i < NOUT; i += THREADS) sm[OFF_B2 + permC(i)] = b2[i];
    __syncthreads();

    // ---- GEMM A: h1 = tanh(x @ W1 + b1), warp owns 8 cols ----
    {
        const int c0 = warp * 8;
        const ulonglong2* bb = (const ulonglong2*)(sm + OFF_B1 + c0);
        ulonglong2 a0[2], a1[2];
        a0[0] = bb[0]; a0[1] = bb[1]; a1[0] = bb[0]; a1[1] = bb[1];
        const float* xr0 = sm + OFF_X + lane * SXS;
        const float* xr1 = sm + OFF_X + (lane + 32) * SXS;
#pragma unroll
        for (int k4 = 0; k4 < KD; k4 += 4) {
            float4 ha = *(const float4*)(xr0 + k4);
            float4 hb = *(const float4*)(xr1 + k4);
            float av[4] = {ha.x, ha.y, ha.z, ha.w};
            float bv[4] = {hb.x, hb.y, hb.z, hb.w};
#pragma unroll
            for (int q = 0; q < 4; q++) {
                ull xa = pk2(av[q], av[q]), xb = pk2(bv[q], bv[q]);
                const ulonglong2* wp = (const ulonglong2*)(sm + OFF_W1 + (k4 + q) * HP + c0);
                ulonglong2 w0 = wp[0], w1 = wp[1];
                a0[0].x = ffma2(xa, w0.x, a0[0].x); a0[0].y = ffma2(xa, w0.y, a0[0].y);
                a0[1].x = ffma2(xa, w1.x, a0[1].x); a0[1].y = ffma2(xa, w1.y, a0[1].y);
                a1[0].x = ffma2(xb, w0.x, a1[0].x); a1[0].y = ffma2(xb, w0.y, a1[0].y);
                a1[1].x = ffma2(xb, w1.x, a1[1].x); a1[1].y = ffma2(xb, w1.y, a1[1].y);
            }
        }
        float v[8];
        upk2(a0[0].x, v[0], v[1]); upk2(a0[0].y, v[2], v[3]);
        upk2(a0[1].x, v[4], v[5]); upk2(a0[1].y, v[6], v[7]);
        if (c0 + 8 <= H) {
            float4 lo = {my_tanhf(v[0]), my_tanhf(v[1]), my_tanhf(v[2]), my_tanhf(v[3])};
            float4 hi = {my_tanhf(v[4]), my_tanhf(v[5]), my_tanhf(v[6]), my_tanhf(v[7])};
            *(float4*)(sm + OFF_H1 + lane * SH + c0) = lo;
            *(float4*)(sm + OFF_H1 + lane * SH + c0 + 4) = hi;
        } else if (c0 < H) {
            float4 lo = {my_tanhf(v[0]), my_tanhf(v[1]), my_tanhf(v[2]), my_tanhf(v[3])};
            *(float4*)(sm + OFF_H1 + lane * SH + c0) = lo;
        }
        upk2(a1[0].x, v[0], v[1]); upk2(a1[0].y, v[2], v[3]);
        upk2(a1[1].x, v[4], v[5]); upk2(a1[1].y, v[6], v[7]);
        if (c0 + 8 <= H) {
            float4 lo = {my_tanhf(v[0]), my_tanhf(v[1]), my_tanhf(v[2]), my_tanhf(v[3])};
            float4 hi = {my_tanhf(v[4]), my_tanhf(v[5]), my_tanhf(v[6]), my_tanhf(v[7])};
            *(float4*)(sm + OFF_H1 + (lane + 32) * SH + c0) = lo;
            *(float4*)(sm + OFF_H1 + (lane + 32) * SH + c0 + 4) = hi;
        } else if (c0 < H) {
            float4 lo = {my_tanhf(v[0]), my_tanhf(v[1]), my_tanhf(v[2]), my_tanhf(v[3])};
            *(float4*)(sm + OFF_H1 + (lane + 32) * SH + c0) = lo;
        }
    }
    __syncthreads();   // h1 done, X/W1 region dead

    // ---- store W4 (padded) from regs, zero-fill pad cols ----
#pragma unroll
    for (int j = 0; j < 20; j++) {
        int idx = tid + j * THREADS;
        if (idx < H * H) {
            int k = idx / H, c = idx - k * H;
            sm[OFF_W4 + k * HP + c] = w4r[j];
        }
    }
    for (int i = tid; i < H * (HP - H); i += THREADS) {
        int k = i / (HP - H), c = H + (i - k * (HP - H));
        sm[OFF_W4 + k * HP + c] = 0.0f;
    }
    // prefetch W2 chunk 0 (hidden under GEMM B)
    const float4* wg = (const float4*)W2;
    float4 pf[4];
#pragma unroll
    for (int j = 0; j < 4; j++) {
        int idx = tid + j * THREADS;
        if (idx < 1920) pf[j] = wg[idx];
    }
    __syncthreads();

    // ---- GEMM B: h2 = tanh(h1 @ W4 + b4) ----
    {
        const int c0 = warp * 8;
        const ulonglong2* bb = (const ulonglong2*)(sm + OFF_B4 + c0);
        ulonglong2 a0[2], a1[2];
        a0[0] = bb[0]; a0[1] = bb[1]; a1[0] = bb[0]; a1[1] = bb[1];
        const float* h0 = sm + OFF_H1 + lane * SH;
        const float* h1r = sm + OFF_H1 + (lane + 32) * SH;
#pragma unroll 5
        for (int k4 = 0; k4 < H; k4 += 4) {
            float4 ha = *(const float4*)(h0 + k4);
            float4 hb = *(const float4*)(h1r + k4);
            float av[4] = {ha.x, ha.y, ha.z, ha.w};
            float bv[4] = {hb.x, hb.y, hb.z, hb.w};
#pragma unroll
            for (int q = 0; q < 4; q++) {
                ull xa = pk2(av[q], av[q]), xb = pk2(bv[q], bv[q]);
                const ulonglong2* wp = (const ulonglong2*)(sm + OFF_W4 + (k4 + q) * HP + c0);
                ulonglong2 w0 = wp[0], w1 = wp[1];
                a0[0].x = ffma2(xa, w0.x, a0[0].x); a0[0].y = ffma2(xa, w0.y, a0[0].y);
                a0[1].x = ffma2(xa, w1.x, a0[1].x); a0[1].y = ffma2(xa, w1.y, a0[1].y);
                a1[0].x = ffma2(xb, w0.x, a1[0].x); a1[0].y = ffma2(xb, w0.y, a1[0].y);
                a1[1].x = ffma2(xb, w1.x, a1[1].x); a1[1].y = ffma2(xb, w1.y, a1[1].y);
            }
        }
        float v[8];
        upk2(a0[0].x, v[0], v[1]); upk2(a0[0].y, v[2], v[3]);
        upk2(a0[1].x, v[4], v[5]); upk2(a0[1].y, v[6], v[7]);
        if (c0 + 8 <= H) {
            float4 lo = {my_tanhf(v[0]), my_tanhf(v[1]), my_tanhf(v[2]), my_tanhf(v[3])};
            float4 hi = {my_tanhf(v[4]), my_tanhf(v[5]), my_tanhf(v[6]), my_tanhf(v[7])};
            *(float4*)(sm + OFF_H2 + lane * SH + c0) = lo;
            *(float4*)(sm + OFF_H2 + lane * SH + c0 + 4) = hi;
        } else if (c0 < H) {
            float4 lo = {my_tanhf(v[0]), my_tanhf(v[1]), my_tanhf(v[2]), my_tanhf(v[3])};
            *(float4*)(sm + OFF_H2 + lane * SH + c0) = lo;
        }
        upk2(a1[0].x, v[0], v[1]); upk2(a1[0].y, v[2], v[3]);
        upk2(a1[1].x, v[4], v[5]); upk2(a1[1].y, v[6], v[7]);
        if (c0 + 8 <= H) {
            float4 lo = {my_tanhf(v[0]), my_tanhf(v[1]), my_tanhf(v[2]), my_tanhf(v[3])};
            float4 hi = {my_tanhf(v[4]), my_tanhf(v[5]), my_tanhf(v[6]), my_tanhf(v[7])};
            *(float4*)(sm + OFF_H2 + (lane + 32) * SH + c0) = lo;
            *(float4*)(sm + OFF_H2 + (lane + 32) * SH + c0 + 4) = hi;
        } else if (c0 < H) {
            float4 lo = {my_tanhf(v[0]), my_tanhf(v[1]), my_tanhf(v[2]), my_tanhf(v[3])};
            *(float4*)(sm + OFF_H2 + (lane + 32) * SH + c0) = lo;
        }
    }
    __syncthreads();   // h2 done, W4 region dead

    // ---- store W2 chunk 0 (permuted cols) ----
#pragma unroll
    for (int j = 0; j < 4; j++) {
        int idx = tid + j * THREADS;
        if (idx < 1920) {
            int k = idx / 96, c4 = (idx - k * 96) * 4;
            int p;
            if (c4 < KD) p = (c4 >> 2) * 24;
            else { int cc = c4 - KD; p = (cc / 20) * 24 + 4 + (cc % 20); }
            *(float4*)(sm + OFF_W2C + k * NOUT + p) = pf[j];
        }
    }
    __syncthreads();

    // ---- GEMM C: out = h2 @ W2 + b2, 5 k-chunks of 20, register-prefetched ----
    const int cw = warp * 24;
    ulonglong2 A0[6], A1[6];
    {
        const ulonglong2* bb = (const ulonglong2*)(sm + OFF_B2 + cw);
#pragma unroll
        for (int j = 0; j < 6; j++) { A0[j] = bb[j]; A1[j] = bb[j]; }
    }
    for (int ch = 0; ch < 5; ch++) {
        if (ch < 4) {
#pragma unroll
            for (int j = 0; j < 4; j++) {
                int idx = tid + j * THREADS;
                if (idx < 1920) pf[j] = wg[(ch + 1) * 1920 + idx];
            }
        }
        const float* h0 = sm + OFF_H2 + lane * SH + ch * 20;
        const float* h1r = sm + OFF_H2 + (lane + 32) * SH + ch * 20;
#pragma unroll
        for (int kq = 0; kq < 20; kq += 4) {
            float4 ha = *(const float4*)(h0 + kq);
            float4 hb = *(const float4*)(h1r + kq);
            float av[4] = {ha.x, ha.y, ha.z, ha.w};
            float bv[4] = {hb.x, hb.y, hb.z, hb.w};
#pragma unroll
            for (int q = 0; q < 4; q++) {
                ull xa = pk2(av[q], av[q]), xb = pk2(bv[q], bv[q]);
                const ulonglong2* wp = (const ulonglong2*)(sm + OFF_W2C + (kq + q) * NOUT + cw);
#pragma unroll
                for (int j = 0; j < 6; j++) {
                    ulonglong2 w = wp[j];
                    A0[j].x = ffma2(xa, w.x, A0[j].x); A0[j].y = ffma2(xa, w.y, A0[j].y);
                    A1[j].x = ffma2(xb, w.x, A1[j].x); A1[j].y = ffma2(xb, w.y, A1[j].y);
                }
            }
        }
        if (ch < 4) {
            __syncthreads();   // everyone done reading this chunk
#pragma unroll
            for (int j = 0; j < 4; j++) {
                int idx = tid + j * THREADS;
                if (idx < 1920) {
                    int k = idx / 96, c4 = (idx - k * 96) * 4;
                    int p;
                    if (c4 < KD) p = (c4 >> 2) * 24;
                    else { int cc = c4 - KD; p = (cc / 20) * 24 + 4 + (cc % 20); }
                    *(float4*)(sm + OFF_W2C + k * NOUT + p) = pf[j];
                }
            }
            __syncthreads();
        }
    }

    // ---- epilogue ----
    float r0v[24], r1v[24];
#pragma unroll
    for (int j = 0; j < 6; j++) {
        upk2(A0[j].x, r0v[4 * j + 0], r0v[4 * j + 1]);
        upk2(A0[j].y, r0v[4 * j + 2], r0v[4 * j + 3]);
        upk2(A1[j].x, r1v[4 * j + 0], r1v[4 * j + 1]);
        upk2(A1[j].y, r1v[4 * j + 2], r1v[4 * j + 3]);
    }
    // stage y1 logits (4 per warp per row) to smem
    {
        float4 s0 = {r0v[0], r0v[1], r0v[2], r0v[3]};
        float4 s1 = {r1v[0], r1v[1], r1v[2], r1v[3]};
        *(float4*)(sm + OFF_SY1 + lane * SY + warp * 4) = s0;
        *(float4*)(sm + OFF_SY1 + (lane + 32) * SY + warp * 4) = s1;
    }
    // prefetch gumbel for this warp's 4 segments x 2 rows
    const float* g0 = gum + (size_t)(row0 + lane) * (KD * 5) + warp * 20;
    const float* g1 = gum + (size_t)(row0 + lane + 32) * (KD * 5) + warp * 20;
    float4 ga[5], gb[5];
#pragma unroll
    for (int s = 0; s < 5; s++) { ga[s] = *(const float4*)(g0 + 4 * s); gb[s] = *(const float4*)(g1 + 4 * s); }
    __syncthreads();

    // y1 softmax: 8 threads per row over 64 logits, write straight to global
    {
        const int row = tid >> 3, sub = tid & 7;
        const float* yr = sm + OFF_SY1 + row * SY;
        float4 v0 = *(const float4*)(yr + sub * 8);
        float4 v1 = *(const float4*)(yr + sub * 8 + 4);
        float vv[8] = {v0.x, v0.y, v0.z, v0.w, v1.x, v1.y, v1.z, v1.w};
        float mx = vv[0];
#pragma unroll
        for (int j = 1; j < 8; j++) mx = fmaxf(mx, vv[j]);
#pragma unroll
        for (int d = 1; d < 8; d <<= 1) mx = fmaxf(mx, __shfl_xor_sync(0xFFFFFFFFu, mx, d));
        float s = 0.0f;
#pragma unroll
        for (int j = 0; j < 8; j++) { vv[j] = my_expf(fmaxf(vv[j] - mx, -80.0f)); s += vv[j]; }
#pragma unroll
        for (int d = 1; d < 8; d <<= 1) s += __shfl_xor_sync(0xFFFFFFFFu, s, d);
        float rs = __frcp_rn(s);
        float* og = out + (size_t)(row0 + row) * NOUT + sub * 8;
        float4 o0 = {vv[0] * rs, vv[1] * rs, vv[2] * rs, vv[3] * rs};
        float4 o1 = {vv[4] * rs, vv[5] * rs, vv[6] * rs, vv[7] * rs};
        *(float4*)og = o0;
        *(float4*)(og + 4) = o1;
    }

    // y2: one-hot argmax over 4 segments x 2 rows, straight to global
    {
        float gaf[20], gbf[20];
#pragma unroll
        for (int s = 0; s < 5; s++) {
            gaf[4 * s] = ga[s].x; gaf[4 * s + 1] = ga[s].y; gaf[4 * s + 2] = ga[s].z; gaf[4 * s + 3] = ga[s].w;
            gbf[4 * s] = gb[s].x; gbf[4 * s + 1] = gb[s].y; gbf[4 * s + 2] = gb[s].z; gbf[4 * s + 3] = gb[s].w;
        }
        float ov[20];
#pragma unroll
        for (int s = 0; s < 4; s++) {
            float best = r0v[4 + 5 * s] + gaf[5 * s];
            int arg = 0;
#pragma unroll
            for (int m = 1; m < 5; m++) {
                float val = r0v[4 + 5 * s + m] + gaf[5 * s + m];
                if (val > best) { best = val; arg = m; }
            }
#pragma unroll
            for (int m = 0; m < 5; m++) ov[5 * s + m] = (m == arg) ? 1.0f : 0.0f;
        }
        float* o0p = out + (size_t)(row0 + lane) * NOUT + KD + warp * 20;
#pragma unroll
        for (int s = 0; s < 5; s++) {
            float4 w = {ov[4 * s], ov[4 * s + 1], ov[4 * s + 2], ov[4 * s + 3]};
            *(float4*)(o0p + 4 * s) = w;
        }
#pragma unroll
        for (int s = 0; s < 4; s++) {
            float best = r1v[4 + 5 * s] + gbf[5 * s];
            int arg = 0;
#pragma unroll
            for (int m = 1; m < 5; m++) {
                float val = r1v[4 + 5 * s + m] + gbf[5 * s + m];
                if (val > best) { best = val; arg = m; }
            }
#pragma unroll
            for (int m = 0; m < 5; m++) ov[5 * s + m] = (m == arg) ? 1.0f : 0.0f;
        }
        float* o1p = out + (size_t)(row0 + lane + 32) * NOUT + KD + warp * 20;
#pragma unroll
        for (int s = 0; s < 5; s++) {
            float4 w = {ov[4 * s], ov[4 * s + 1], ov[4 * s + 2], ov[4 * s + 3]};
            *(float4*)(o1p + 4 * s) = w;
        }
    }
}

extern "C" void kernel_launch(void* const* d_in, const int* in_sizes, int n_in,
                              void* d_out, int out_size) {
    const float* x   = (const float*)d_in[0];
    const float* W1  = (const float*)d_in[1];
    const float* b1  = (const float*)d_in[2];
    const float* W4  = (const float*)d_in[3];
    const float* b4  = (const float*)d_in[4];
    const float* W2  = (const float*)d_in[5];
    const float* b2  = (const float*)d_in[6];
    const float* gum = (const float*)d_in[7];
    float* out = (float*)d_out;

    int B = in_sizes[0] / KD;
    int grid = B / TM;

    cudaFuncSetAttribute(fused_mlp_gumbel,
                         cudaFuncAttributeMaxDynamicSharedMemorySize, SMEM_BYTES);
    fused_mlp_gumbel<<<grid, THREADS, SMEM_BYTES>>>(x, W1, b1, W4, b4, W2, b2, gum, out);
}